// round 1
// baseline (speedup 1.0000x reference)
#include <cuda_runtime.h>
#include <cuda_bf16.h>

// ROI pooling (crop + 7x7 bilinear resize), NHWC.
// img:  (1, 128, 128, 1024) fp32
// rois: (1, 1000, 4) int32  -> {x, y, w, h}
// out:  (1, 1000, 7, 7, 1024) fp32
//
// One CTA per (roi, py, px). 256 threads x float4 covers C=1024 exactly.

#define H_IMG 128
#define W_IMG 128
#define C_IMG 1024
#define POOL 7
#define NUM_ROIS 1000

__global__ __launch_bounds__(256, 8)
void roi_pool_kernel(const float* __restrict__ img,
                     const int*   __restrict__ rois,
                     float*       __restrict__ out)
{
    const int b  = blockIdx.x;            // 0 .. 48999
    const int px = b % POOL;
    const int py = (b / POOL) % POOL;
    const int r  = b / (POOL * POOL);
    const int c4 = threadIdx.x;           // float4 channel index, 0..255

    // roi = {x, y, w, h}; 16B-aligned (r*16 bytes from a cudaMalloc base)
    const int4 roi = __ldg(((const int4*)rois) + r);
    const int rx = roi.x, ry = roi.y, rw = roi.z, rh = roi.w;

    // y axis: f = (py+0.5)*h/7 - 0.5, clamp [0, h-1], split floor/next/weight
    const float hf = (float)rh;
    float fy = (py + 0.5f) * (hf * (1.0f / POOL)) - 0.5f;
    fy = fminf(fmaxf(fy, 0.0f), fmaxf(hf - 1.0f, 0.0f));
    int   iy0 = (int)floorf(fy);
    const float wy = fy - (float)iy0;
    int   iy1 = min(iy0 + 1, rh - 1);
    iy0 += ry;  iy1 += ry;

    // x axis
    const float wf = (float)rw;
    float fx = (px + 0.5f) * (wf * (1.0f / POOL)) - 0.5f;
    fx = fminf(fmaxf(fx, 0.0f), fmaxf(wf - 1.0f, 0.0f));
    int   ix0 = (int)floorf(fx);
    const float wx = fx - (float)ix0;
    int   ix1 = min(ix0 + 1, rw - 1);
    ix0 += rx;  ix1 += rx;

    const float4* row0 = (const float4*)(img + ((size_t)iy0 * W_IMG) * C_IMG);
    const float4* row1 = (const float4*)(img + ((size_t)iy1 * W_IMG) * C_IMG);
    const int cpp = C_IMG / 4;  // float4s per pixel = 256

    const float4 v00 = __ldg(row0 + (size_t)ix0 * cpp + c4);
    const float4 v01 = __ldg(row0 + (size_t)ix1 * cpp + c4);
    const float4 v10 = __ldg(row1 + (size_t)ix0 * cpp + c4);
    const float4 v11 = __ldg(row1 + (size_t)ix1 * cpp + c4);

    const float wx1 = 1.0f - wx;
    const float wy1 = 1.0f - wy;

    float4 o;
    {
        float t, bo;
        t  = v00.x * wx1 + v01.x * wx;
        bo = v10.x * wx1 + v11.x * wx;
        o.x = t * wy1 + bo * wy;
        t  = v00.y * wx1 + v01.y * wx;
        bo = v10.y * wx1 + v11.y * wx;
        o.y = t * wy1 + bo * wy;
        t  = v00.z * wx1 + v01.z * wx;
        bo = v10.z * wx1 + v11.z * wx;
        o.z = t * wy1 + bo * wy;
        t  = v00.w * wx1 + v01.w * wx;
        bo = v10.w * wx1 + v11.w * wx;
        o.w = t * wy1 + bo * wy;
    }

    ((float4*)out)[(size_t)b * cpp + c4] = o;
}

extern "C" void kernel_launch(void* const* d_in, const int* in_sizes, int n_in,
                              void* d_out, int out_size)
{
    const float* img  = (const float*)d_in[0];
    const int*   rois = (const int*)d_in[1];
    float*       out  = (float*)d_out;

    dim3 grid(NUM_ROIS * POOL * POOL);
    dim3 block(256);
    roi_pool_kernel<<<grid, block>>>(img, rois, out);
}

// round 2
// speedup vs baseline: 1.2058x; 1.2058x over previous
#include <cuda_runtime.h>
#include <cuda_bf16.h>

// ROI pooling (crop + 7x7 bilinear resize), NHWC.
// img:  (1, 128, 128, 1024) fp32
// rois: (1, 1000, 4) int32  -> {x, y, w, h}
// out:  (1, 1000, 7, 7, 1024) fp32
//
// One CTA per (roi, py): 256 threads x float4 covers C=1024; each thread
// produces the 7 px outputs of that row -> 28 independent loads in flight.

#define H_IMG 128
#define W_IMG 128
#define C_IMG 1024
#define POOL 7
#define NUM_ROIS 1000
#define CPP (C_IMG / 4)   // float4s per pixel = 256

__global__ __launch_bounds__(256, 4)
void roi_pool_kernel(const float* __restrict__ img,
                     const int*   __restrict__ rois,
                     float*       __restrict__ out)
{
    const int b  = blockIdx.x;            // 0 .. 6999
    const int py = b % POOL;
    const int r  = b / POOL;
    const int c4 = threadIdx.x;           // float4 channel index, 0..255

    const int4 roi = __ldg(((const int4*)rois) + r);
    const int rx = roi.x, ry = roi.y, rw = roi.z, rh = roi.w;

    // y axis (uniform across CTA): f = (py+0.5)*h/7 - 0.5, clamp, split
    const float hf = (float)rh;
    float fy = (py + 0.5f) * (hf * (1.0f / POOL)) - 0.5f;
    fy = fminf(fmaxf(fy, 0.0f), fmaxf(hf - 1.0f, 0.0f));
    int   iy0 = (int)floorf(fy);
    const float wy  = fy - (float)iy0;
    const float wy1 = 1.0f - wy;
    int   iy1 = min(iy0 + 1, rh - 1);
    iy0 += ry;  iy1 += ry;

    const float4* __restrict__ row0 =
        (const float4*)(img + ((size_t)iy0 * W_IMG) * C_IMG) + c4;
    const float4* __restrict__ row1 =
        (const float4*)(img + ((size_t)iy1 * W_IMG) * C_IMG) + c4;

    // x axis for all 7 px (uniform scalars)
    const float wf  = (float)rw;
    const float sfx = wf * (1.0f / POOL);
    const float xcl = fmaxf(wf - 1.0f, 0.0f);

    float4* __restrict__ optr =
        (float4*)out + ((size_t)(r * POOL + py) * POOL) * CPP + c4;

    #pragma unroll
    for (int px = 0; px < POOL; ++px) {
        float fx = (px + 0.5f) * sfx - 0.5f;
        fx = fminf(fmaxf(fx, 0.0f), xcl);
        int   ix0 = (int)floorf(fx);
        const float wx  = fx - (float)ix0;
        const float wx1 = 1.0f - wx;
        int   ix1 = min(ix0 + 1, rw - 1);
        ix0 += rx;  ix1 += rx;

        const float4 v00 = __ldg(row0 + (size_t)ix0 * CPP);
        const float4 v01 = __ldg(row0 + (size_t)ix1 * CPP);
        const float4 v10 = __ldg(row1 + (size_t)ix0 * CPP);
        const float4 v11 = __ldg(row1 + (size_t)ix1 * CPP);

        float4 o;
        o.x = (v00.x * wx1 + v01.x * wx) * wy1 + (v10.x * wx1 + v11.x * wx) * wy;
        o.y = (v00.y * wx1 + v01.y * wx) * wy1 + (v10.y * wx1 + v11.y * wx) * wy;
        o.z = (v00.z * wx1 + v01.z * wx) * wy1 + (v10.z * wx1 + v11.z * wx) * wy;
        o.w = (v00.w * wx1 + v01.w * wx) * wy1 + (v10.w * wx1 + v11.w * wx) * wy;

        __stcs(optr + (size_t)px * CPP, o);
    }
}

extern "C" void kernel_launch(void* const* d_in, const int* in_sizes, int n_in,
                              void* d_out, int out_size)
{
    const float* img  = (const float*)d_in[0];
    const int*   rois = (const int*)d_in[1];
    float*       out  = (float*)d_out;

    dim3 grid(NUM_ROIS * POOL);
    dim3 block(256);
    roi_pool_kernel<<<grid, block>>>(img, rois, out);
}